// round 10
// baseline (speedup 1.0000x reference)
#include <cuda_runtime.h>
#include <math.h>

#define N_LEVELS      16
#define HASHMAP_SIZE  (1u << 19)
#define HASH_MASK     (HASHMAP_SIZE - 1u)
#define P2            2654435761u
#define P3            805459861u

struct ResTable {
    int res[N_LEVELS];
};

// 4 lanes per point: lane owns corner pair (i,j) = ((c2>>1), c2&1), lerps the
// z-pair in-lane, 2-stage butterfly over the 4-lane group. 8 points per warp.
__global__ void __launch_bounds__(256)
hashenc_kernel(const float* __restrict__ pos,
               const float* __restrict__ emb,
               float* __restrict__ out,
               ResTable rt,
               int n_points)
{
    const int tid  = blockIdx.x * blockDim.x + threadIdx.x;
    const int lane = threadIdx.x & 31;
    const int c2   = lane & 3;          // (i<<1)|j
    const int sub  = lane >> 2;         // point slot within warp (0..7)
    const int p    = (tid >> 5) * 8 + sub;

    const bool valid = (p < n_points);
    const int  pp    = valid ? p : 0;

    const unsigned bi = (c2 >> 1) & 1;  // x corner bit
    const unsigned bj =  c2       & 1;  // y corner bit

    const float px = pos[pp * 3 + 0];
    const float py = pos[pp * 3 + 1];
    const float pz = pos[pp * 3 + 2];

    // lane c2 keeps level-pairs m = c2 and m = c2+4  (levels 2m, 2m+1)
    float acc[8];

#pragma unroll
    for (int l = 0; l < N_LEVELS; ++l) {
        const int   res  = rt.res[l];
        const float fres = (float)res;

        const float sx = px * fres, sy = py * fres, sz = pz * fres;
        const float fx = floorf(sx), fy = floorf(sy), fz = floorf(sz);
        const float wx = sx - fx,   wy = sy - fy,   wz = sz - fz;

        const unsigned ux = (unsigned)(int)fx + bi;
        const unsigned uy = (unsigned)(int)fy + bj;
        const unsigned uz = (unsigned)(int)fz;

        const unsigned r1 = (unsigned)(res + 1);
        const bool dense =
            ((long long)r1 * (long long)r1 * (long long)r1) <= (long long)HASHMAP_SIZE;

        unsigned idx0, idx1;                 // z-pair entries (k=0, k=1)
        if (dense) {
            idx0 = ux * (r1 * r1) + uy * r1 + uz;
            idx1 = idx0 + 1u;
        } else {
            const unsigned hxy = ux ^ (uy * P2);
            const unsigned hz  = uz * P3;
            idx0 = (hxy ^ hz)        & HASH_MASK;
            idx1 = (hxy ^ (hz + P3)) & HASH_MASK;
        }

        const float2* __restrict__ table =
            reinterpret_cast<const float2*>(emb) + (size_t)l * HASHMAP_SIZE;
        const float2 f0 = __ldg(&table[idx0]);
        const float2 f1 = __ldg(&table[idx1]);

        // z-lerp in-lane (matches reference ordering: c = f0*(1-wz) + f1*wz)
        const float omz = 1.0f - wz;
        const float zx  = f0.x * omz + f1.x * wz;
        const float zy  = f0.y * omz + f1.y * wz;

        // (i,j) weight for this lane
        const float ax = bi ? wx : (1.0f - wx);
        const float ay = bj ? wy : (1.0f - wy);
        const float w  = ax * ay;

        float v0 = zx * w;
        float v1 = zy * w;

        // 2-stage butterfly across the 4-lane group (xor 2 = x, xor 1 = y)
        v0 += __shfl_xor_sync(0xffffffffu, v0, 2);
        v1 += __shfl_xor_sync(0xffffffffu, v1, 2);
        v0 += __shfl_xor_sync(0xffffffffu, v0, 1);
        v1 += __shfl_xor_sync(0xffffffffu, v1, 1);

        // keeper: pair m = l>>1; lane (m&3) keeps it; half = m>>2
        const int m = l >> 1;
        if ((m & 3) == c2) {
            const int base = (m >> 2) * 4 + (l & 1) * 2;
            acc[base + 0] = v0;
            acc[base + 1] = v1;
        }
    }

    if (valid) {
        float4* __restrict__ o4 = reinterpret_cast<float4*>(out);
        // lane-consecutive addresses: lanes 0..3 -> slots 0..3, then 4..7
        o4[(size_t)p * 8 + c2]     = make_float4(acc[0], acc[1], acc[2], acc[3]);
        o4[(size_t)p * 8 + 4 + c2] = make_float4(acc[4], acc[5], acc[6], acc[7]);
    }
}

extern "C" void kernel_launch(void* const* d_in, const int* in_sizes, int n_in,
                              void* d_out, int out_size)
{
    const float* positions  = (const float*)d_in[0];   // [N_POINTS, 3] f32
    const float* embeddings = (const float*)d_in[1];   // [16, 2^19, 2] f32
    float*       out        = (float*)d_out;           // [N_POINTS, 32] f32

    const int n_points = in_sizes[0] / 3;

    // Mirror numpy exactly in double precision (libm exp/log/pow)
    ResTable rt;
    const double scale = exp((log(2048.0) - log(16.0)) / 15.0);
    for (int l = 0; l < N_LEVELS; ++l) {
        rt.res[l] = (int)floor(16.0 * pow(scale, (double)l));
    }

    // 4 threads per point
    const long long total_threads = (long long)n_points * 4;
    const int threads = 256;
    const int blocks  = (int)((total_threads + threads - 1) / threads);
    hashenc_kernel<<<blocks, threads>>>(positions, embeddings, out, rt, n_points);
}

// round 11
// speedup vs baseline: 1.0808x; 1.0808x over previous
#include <cuda_runtime.h>
#include <math.h>

#define N_LEVELS      16
#define HASHMAP_SIZE  (1u << 19)
#define HASH_MASK     (HASHMAP_SIZE - 1u)
#define P2            2654435761u
#define P3            805459861u

#define KEY_BITS_AXIS 7
#define HISTO_SIZE    (1u << (3 * KEY_BITS_AXIS))   // 2^21 buckets
#define SCAN_BLOCKS   (HISTO_SIZE / 1024)           // 2048
#define MAX_POINTS    2200000

struct ResTable {
    int res[N_LEVELS];
};

// ---- static scratch ----
__device__ unsigned g_histo[HISTO_SIZE];   // counts -> excl-within-block -> cursors
__device__ unsigned g_bsum[SCAN_BLOCKS];   // exclusive block offsets
__device__ unsigned g_keys[MAX_POINTS];
__device__ float4   g_spos[MAX_POINTS];    // sorted (x, y, z, orig_idx)

// ---------------- sort pre-pass ----------------

__device__ __forceinline__ unsigned part1by2(unsigned x) {
    x &= 0x3ff;
    x = (x | (x << 16)) & 0x030000FF;
    x = (x | (x << 8))  & 0x0300F00F;
    x = (x | (x << 4))  & 0x030C30C3;
    x = (x | (x << 2))  & 0x09249249;
    return x;
}

__global__ void k_key_histo(const float* __restrict__ pos, int n) {
    int i = blockIdx.x * blockDim.x + threadIdx.x;
    if (i >= n) return;
    const int R = 1 << KEY_BITS_AXIS;
    unsigned kx = min(R - 1, max(0, (int)(pos[i * 3 + 0] * (float)R)));
    unsigned ky = min(R - 1, max(0, (int)(pos[i * 3 + 1] * (float)R)));
    unsigned kz = min(R - 1, max(0, (int)(pos[i * 3 + 2] * (float)R)));
    unsigned key = part1by2(kx) | (part1by2(ky) << 1) | (part1by2(kz) << 2);
    g_keys[i] = key;
    atomicAdd(&g_histo[key], 1u);
}

// Per-1024-bucket exclusive scan (warp-shuffle based; proven in R8).
__global__ void k_scan1() {
    __shared__ unsigned wsum[32];
    const unsigned t    = threadIdx.x;
    const unsigned lane = t & 31;
    const unsigned warp = t >> 5;
    const unsigned i    = blockIdx.x * 1024 + t;

    const unsigned v = g_histo[i];
    unsigned s = v;
#pragma unroll
    for (int o = 1; o < 32; o <<= 1) {
        unsigned u = __shfl_up_sync(0xffffffffu, s, o);
        if (lane >= (unsigned)o) s += u;
    }
    if (lane == 31) wsum[warp] = s;
    __syncthreads();
    if (warp == 0) {
        unsigned w = wsum[lane];
#pragma unroll
        for (int o = 1; o < 32; o <<= 1) {
            unsigned u = __shfl_up_sync(0xffffffffu, w, o);
            if (lane >= (unsigned)o) w += u;
        }
        wsum[lane] = w;
    }
    __syncthreads();
    const unsigned base = (warp == 0) ? 0u : wsum[warp - 1];
    g_histo[i] = base + s - v;                       // exclusive within block
    if (t == 1023) g_bsum[blockIdx.x] = base + s;    // block total
}

// Exclusive scan of 2048 block totals, one block of 1024 (proven in R7).
__global__ void k_scan2() {
    __shared__ unsigned s[1024];
    const unsigned t = threadIdx.x;
    const unsigned a = g_bsum[2 * t];
    const unsigned b = g_bsum[2 * t + 1];
    const unsigned sum = a + b;
    s[t] = sum;
    __syncthreads();
    for (int o = 1; o < 1024; o <<= 1) {
        unsigned add = (t >= (unsigned)o) ? s[t - o] : 0u;
        __syncthreads();
        s[t] += add;
        __syncthreads();
    }
    const unsigned excl = s[t] - sum;
    g_bsum[2 * t]     = excl;
    g_bsum[2 * t + 1] = excl + a;
}

// ILP-4 scatter with fused addback: 4 independent atomic->store chains/thread.
__global__ void k_scatter(const float* __restrict__ pos, int n, int stride) {
    const int i0 = blockIdx.x * blockDim.x + threadIdx.x;
#pragma unroll
    for (int j = 0; j < 4; ++j) {
        const int i = i0 + j * stride;
        if (i < n) {
            const unsigned key = g_keys[i];
            const float x = pos[i * 3 + 0];
            const float y = pos[i * 3 + 1];
            const float z = pos[i * 3 + 2];
            const unsigned dst = g_bsum[key >> 10] + atomicAdd(&g_histo[key], 1u);
            g_spos[dst] = make_float4(x, y, z, __int_as_float(i));
        }
    }
}

// ---------------- main encode (R5 body, sorted input; proven in R7) ----------------

__global__ void __launch_bounds__(256)
hashenc_kernel(const float* __restrict__ emb,
               float* __restrict__ out,
               ResTable rt,
               int n_points)
{
    const int tid   = blockIdx.x * blockDim.x + threadIdx.x;
    const int lane  = threadIdx.x & 31;
    const int c     = lane & 7;
    const int sub   = lane >> 3;
    const int pslot = (tid >> 5) * 4 + sub;

    const bool valid = (pslot < n_points);
    const int  ps    = valid ? pslot : 0;

    const unsigned bi = (c >> 2) & 1;
    const unsigned bj = (c >> 1) & 1;
    const unsigned bk =  c       & 1;

    const float4 sp = __ldg(&g_spos[ps]);
    const float px = sp.x, py = sp.y, pz = sp.z;
    const int orig = __float_as_int(sp.w);

    float acc0 = 0.f, acc1 = 0.f, acc2 = 0.f, acc3 = 0.f;

#pragma unroll
    for (int l = 0; l < N_LEVELS; ++l) {
        const int   res  = rt.res[l];
        const float fres = (float)res;

        const float sx = px * fres, sy = py * fres, sz = pz * fres;
        const float fx = floorf(sx), fy = floorf(sy), fz = floorf(sz);
        const float wx = sx - fx,   wy = sy - fy,   wz = sz - fz;

        const unsigned ux = (unsigned)(int)fx + bi;
        const unsigned uy = (unsigned)(int)fy + bj;
        const unsigned uz = (unsigned)(int)fz + bk;

        const unsigned r1 = (unsigned)(res + 1);
        const bool dense =
            ((long long)r1 * (long long)r1 * (long long)r1) <= (long long)HASHMAP_SIZE;

        unsigned idx;
        if (dense) {
            idx = ux * (r1 * r1) + uy * r1 + uz;
        } else {
            idx = (ux ^ (uy * P2) ^ (uz * P3)) & HASH_MASK;
        }

        const float2* __restrict__ table =
            reinterpret_cast<const float2*>(emb) + (size_t)l * HASHMAP_SIZE;
        const float2 f = __ldg(&table[idx]);

        const float ax = bi ? wx : (1.0f - wx);
        const float ay = bj ? wy : (1.0f - wy);
        const float az = bk ? wz : (1.0f - wz);
        const float w  = ax * ay * az;

        float v0 = f.x * w;
        float v1 = f.y * w;

        v0 += __shfl_xor_sync(0xffffffffu, v0, 4);
        v1 += __shfl_xor_sync(0xffffffffu, v1, 4);
        v0 += __shfl_xor_sync(0xffffffffu, v0, 2);
        v1 += __shfl_xor_sync(0xffffffffu, v1, 2);
        v0 += __shfl_xor_sync(0xffffffffu, v0, 1);
        v1 += __shfl_xor_sync(0xffffffffu, v1, 1);

        if ((l >> 1) == c) {
            if (l & 1) { acc2 = v0; acc3 = v1; }
            else       { acc0 = v0; acc1 = v1; }
        }
    }

    if (valid) {
        float4* __restrict__ o4 = reinterpret_cast<float4*>(out);
        o4[(size_t)orig * 8 + c] = make_float4(acc0, acc1, acc2, acc3);
    }
}

extern "C" void kernel_launch(void* const* d_in, const int* in_sizes, int n_in,
                              void* d_out, int out_size)
{
    const float* positions  = (const float*)d_in[0];   // [N_POINTS, 3] f32
    const float* embeddings = (const float*)d_in[1];   // [16, 2^19, 2] f32
    float*       out        = (float*)d_out;           // [N_POINTS, 32] f32

    const int n_points = in_sizes[0] / 3;

    ResTable rt;
    const double scale = exp((log(2048.0) - log(16.0)) / 15.0);
    for (int l = 0; l < N_LEVELS; ++l) {
        rt.res[l] = (int)floor(16.0 * pow(scale, (double)l));
    }

    // ---- sort pre-pass ----
    void* histo_ptr = nullptr;
    cudaGetSymbolAddress(&histo_ptr, g_histo);
    cudaMemsetAsync(histo_ptr, 0, HISTO_SIZE * sizeof(unsigned));

    const int pblocks = (n_points + 255) / 256;
    k_key_histo<<<pblocks, 256>>>(positions, n_points);
    k_scan1<<<SCAN_BLOCKS, 1024>>>();
    k_scan2<<<1, 1024>>>();
    const int quarter   = (n_points + 3) / 4;
    const int sblocks   = (quarter + 255) / 256;
    const int sstride   = sblocks * 256;
    k_scatter<<<sblocks, 256>>>(positions, n_points, sstride);

    // ---- main encode: 8 threads per point ----
    const long long total_threads = (long long)n_points * 8;
    const int threads = 256;
    const int blocks  = (int)((total_threads + threads - 1) / threads);
    hashenc_kernel<<<blocks, threads>>>(embeddings, out, rt, n_points);
}